// round 1
// baseline (speedup 1.0000x reference)
#include <cuda_runtime.h>
#include <math.h>

// Problem constants
#define Bn   2
#define Tn   2048
#define Dn   1024
#define Hn   16
#define DHn  64
#define DFFn 2730
#define Mn   (Bn*Tn)          // 4096 rows
#define EPSn 1e-5f

// ---------------------------------------------------------------------------
// Scratch (device globals — no dynamic allocation allowed)
// ---------------------------------------------------------------------------
__device__ float g_h  [Mn*Dn];        // rmsnorm(x)
__device__ float g_q  [Mn*Hn*DHn];
__device__ float g_k  [Mn*Hn*DHn];
__device__ float g_v  [Mn*Hn*DHn];
__device__ float g_ctx[Mn*Hn*DHn];
__device__ float g_x1 [Mn*Dn];        // x + ctx@Wo
__device__ float g_h2 [Mn*Dn];        // rmsnorm(x1)
__device__ float g_fa [Mn*DFFn];      // h2@W1 then silu*b in place
__device__ float g_fb [Mn*DFFn];      // h2@W2

// ---------------------------------------------------------------------------
// RMSNorm: one block per row, 256 threads, D=1024 → one float4 per thread
// ---------------------------------------------------------------------------
__global__ void rmsnorm_kernel(const float* __restrict__ x,
                               const float* __restrict__ g,
                               float* __restrict__ out) {
    const int row = blockIdx.x;
    const int t   = threadIdx.x;
    const float4* xr = (const float4*)(x + (size_t)row * Dn);
    float4 xv = xr[t];
    float ss = xv.x*xv.x + xv.y*xv.y + xv.z*xv.z + xv.w*xv.w;
    #pragma unroll
    for (int o = 16; o > 0; o >>= 1)
        ss += __shfl_xor_sync(0xffffffffu, ss, o);
    __shared__ float red[8];
    if ((t & 31) == 0) red[t >> 5] = ss;
    __syncthreads();
    float tot = red[0] + red[1] + red[2] + red[3] + red[4] + red[5] + red[6] + red[7];
    float rs = rsqrtf(tot * (1.0f / Dn) + EPSn);
    float4 gv = ((const float4*)g)[t];
    float4 o4 = make_float4(gv.x * xv.x * rs, gv.y * xv.y * rs,
                            gv.z * xv.z * rs, gv.w * xv.w * rs);
    ((float4*)(out + (size_t)row * Dn))[t] = o4;
}

// ---------------------------------------------------------------------------
// GEMM: C[M,N] = A[M,K] @ B[K,N]  (+ Res if ADD). Row-major all.
// 128x128 block tile, K-step 8, 256 threads, 8x8 per-thread micro-tile.
// M must be a multiple of 128 (always 4096 here); N, K arbitrary.
// ---------------------------------------------------------------------------
template<int ADD>
__global__ void gemm_kernel(const float* __restrict__ A,
                            const float* __restrict__ Bm,
                            const float* __restrict__ Res,
                            float* __restrict__ C,
                            int M, int N, int K) {
    __shared__ __align__(16) float As[8 * 132];   // [k][row], pad 132 (conflict-free)
    __shared__ __align__(16) float Bs[8 * 128];   // [k][col]
    const int tid = threadIdx.x;
    const int tx = tid & 15, ty = tid >> 4;
    const int rowBase = blockIdx.y * 128;
    const int colBase = blockIdx.x * 128;

    float acc[8][8];
    #pragma unroll
    for (int i = 0; i < 8; ++i)
        #pragma unroll
        for (int j = 0; j < 8; ++j) acc[i][j] = 0.0f;

    const int numK = (K + 7) >> 3;
    for (int kt = 0; kt < numK; ++kt) {
        const int k0 = kt << 3;
        #pragma unroll
        for (int l = 0; l < 4; ++l) {              // A tile: 128 rows x 8 k
            int idx = tid + (l << 8);
            int r = idx >> 3, kk = idx & 7;
            float val = (k0 + kk < K) ? A[(size_t)(rowBase + r) * K + k0 + kk] : 0.0f;
            As[kk * 132 + r] = val;
        }
        #pragma unroll
        for (int l = 0; l < 4; ++l) {              // B tile: 8 k x 128 cols
            int idx = tid + (l << 8);
            int kk = idx >> 7, cc = idx & 127;
            int col = colBase + cc;
            float val = (k0 + kk < K && col < N) ? Bm[(size_t)(k0 + kk) * N + col] : 0.0f;
            Bs[kk * 128 + cc] = val;
        }
        __syncthreads();
        #pragma unroll
        for (int kk = 0; kk < 8; ++kk) {
            float4 a0 = *(const float4*)&As[kk * 132 + ty * 8];
            float4 a1 = *(const float4*)&As[kk * 132 + ty * 8 + 4];
            float4 b0 = *(const float4*)&Bs[kk * 128 + tx * 8];
            float4 b1 = *(const float4*)&Bs[kk * 128 + tx * 8 + 4];
            float av[8] = {a0.x, a0.y, a0.z, a0.w, a1.x, a1.y, a1.z, a1.w};
            float bv[8] = {b0.x, b0.y, b0.z, b0.w, b1.x, b1.y, b1.z, b1.w};
            #pragma unroll
            for (int i = 0; i < 8; ++i)
                #pragma unroll
                for (int j = 0; j < 8; ++j)
                    acc[i][j] += av[i] * bv[j];
        }
        __syncthreads();
    }
    #pragma unroll
    for (int i = 0; i < 8; ++i) {
        int row = rowBase + ty * 8 + i;
        #pragma unroll
        for (int j = 0; j < 8; ++j) {
            int col = colBase + tx * 8 + j;
            if (col < N) {
                float r = acc[i][j];
                if (ADD) r += Res[(size_t)row * N + col];
                C[(size_t)row * N + col] = r;
            }
        }
    }
}

// ---------------------------------------------------------------------------
// Flash attention, causal, scale = DH^-0.5 = 0.125. ALiBi bias is identically
// zero on the causal region (dist = clip(j-i,0) == 0 for j<=i), so omitted.
// Grid: (32 q-tiles of 64, B*H=32). 256 threads = 16x16; each thread owns a
// 4(row) x 4(col) micro-tile of S and a 4(row) x 4(dim) micro-tile of O.
// ---------------------------------------------------------------------------
#define ATT_STRIDE 68           // 64 + 4 pad: float4-aligned, bank-friendly
#define ATT_SMEM   (4 * 64 * ATT_STRIDE * 4)   // Qs,Ks,Vs,Ss = 69632 bytes

__global__ void attn_kernel(const float* __restrict__ q,
                            const float* __restrict__ k,
                            const float* __restrict__ v,
                            float* __restrict__ ctx) {
    extern __shared__ float sm[];
    float* Qs = sm;
    float* Ks = sm + 64 * ATT_STRIDE;
    float* Vs = sm + 2 * 64 * ATT_STRIDE;
    float* Ss = sm + 3 * 64 * ATT_STRIDE;

    const int qt = blockIdx.x;
    const int bh = blockIdx.y;
    const int b = bh >> 4, h = bh & 15;
    const int tid = threadIdx.x;
    const int tx = tid & 15, ty = tid >> 4;
    const size_t hoff = (size_t)b * Tn * 1024 + (size_t)h * 64;

    // Load Q tile (pre-scaled)
    #pragma unroll
    for (int l = 0; l < 16; ++l) {
        int idx = tid + (l << 8);
        int j = idx >> 6, d = idx & 63;
        Qs[j * ATT_STRIDE + d] = q[hoff + (size_t)(qt * 64 + j) * 1024 + d] * 0.125f;
    }

    float m[4], lsum[4], acc[4][4];
    #pragma unroll
    for (int ri = 0; ri < 4; ++ri) {
        m[ri] = -1e30f; lsum[ri] = 0.0f;
        #pragma unroll
        for (int di = 0; di < 4; ++di) acc[ri][di] = 0.0f;
    }
    __syncthreads();

    for (int kt = 0; kt <= qt; ++kt) {
        #pragma unroll
        for (int l = 0; l < 16; ++l) {
            int idx = tid + (l << 8);
            int j = idx >> 6, d = idx & 63;
            size_t g = hoff + (size_t)(kt * 64 + j) * 1024 + d;
            Ks[j * ATT_STRIDE + d] = k[g];
            Vs[j * ATT_STRIDE + d] = v[g];
        }
        __syncthreads();

        // S = Q K^T (64x64), 4x4 per thread
        float s[4][4];
        #pragma unroll
        for (int ri = 0; ri < 4; ++ri)
            #pragma unroll
            for (int ji = 0; ji < 4; ++ji) s[ri][ji] = 0.0f;

        #pragma unroll 4
        for (int d = 0; d < 64; d += 4) {
            float4 qv[4], kv[4];
            #pragma unroll
            for (int ri = 0; ri < 4; ++ri)
                qv[ri] = *(const float4*)&Qs[(ty * 4 + ri) * ATT_STRIDE + d];
            #pragma unroll
            for (int ji = 0; ji < 4; ++ji)
                kv[ji] = *(const float4*)&Ks[(tx * 4 + ji) * ATT_STRIDE + d];
            #pragma unroll
            for (int ri = 0; ri < 4; ++ri)
                #pragma unroll
                for (int ji = 0; ji < 4; ++ji)
                    s[ri][ji] += qv[ri].x * kv[ji].x + qv[ri].y * kv[ji].y
                               + qv[ri].z * kv[ji].z + qv[ri].w * kv[ji].w;
        }

        if (kt == qt) {    // causal mask on diagonal tile only
            #pragma unroll
            for (int ri = 0; ri < 4; ++ri)
                #pragma unroll
                for (int ji = 0; ji < 4; ++ji)
                    if (tx * 4 + ji > ty * 4 + ri) s[ri][ji] = -1e30f;
        }

        // Online softmax per row (row owned by 16 tx-threads; reduce via shfl)
        #pragma unroll
        for (int ri = 0; ri < 4; ++ri) {
            float mx = fmaxf(fmaxf(s[ri][0], s[ri][1]), fmaxf(s[ri][2], s[ri][3]));
            #pragma unroll
            for (int o = 8; o > 0; o >>= 1)
                mx = fmaxf(mx, __shfl_xor_sync(0xffffffffu, mx, o));
            float mnew = fmaxf(m[ri], mx);
            float ps = __expf(m[ri] - mnew);
            m[ri] = mnew;
            float ls = 0.0f;
            #pragma unroll
            for (int ji = 0; ji < 4; ++ji) {
                float p = __expf(s[ri][ji] - mnew);
                s[ri][ji] = p;
                ls += p;
            }
            #pragma unroll
            for (int o = 8; o > 0; o >>= 1)
                ls += __shfl_xor_sync(0xffffffffu, ls, o);
            lsum[ri] = lsum[ri] * ps + ls;
            #pragma unroll
            for (int di = 0; di < 4; ++di) acc[ri][di] *= ps;
            #pragma unroll
            for (int ji = 0; ji < 4; ++ji)
                Ss[(ty * 4 + ri) * ATT_STRIDE + tx * 4 + ji] = s[ri][ji];
        }
        __syncthreads();

        // O += P V (64x64), 4 rows x 4 dims per thread
        #pragma unroll 4
        for (int j = 0; j < 64; j += 4) {
            float4 pr[4];
            #pragma unroll
            for (int ri = 0; ri < 4; ++ri)
                pr[ri] = *(const float4*)&Ss[(ty * 4 + ri) * ATT_STRIDE + j];
            float pa[4][4];
            #pragma unroll
            for (int ri = 0; ri < 4; ++ri) {
                pa[ri][0] = pr[ri].x; pa[ri][1] = pr[ri].y;
                pa[ri][2] = pr[ri].z; pa[ri][3] = pr[ri].w;
            }
            #pragma unroll
            for (int jj = 0; jj < 4; ++jj) {
                float4 vv = *(const float4*)&Vs[(j + jj) * ATT_STRIDE + tx * 4];
                #pragma unroll
                for (int ri = 0; ri < 4; ++ri) {
                    acc[ri][0] += pa[ri][jj] * vv.x;
                    acc[ri][1] += pa[ri][jj] * vv.y;
                    acc[ri][2] += pa[ri][jj] * vv.z;
                    acc[ri][3] += pa[ri][jj] * vv.w;
                }
            }
        }
        __syncthreads();
    }

    #pragma unroll
    for (int ri = 0; ri < 4; ++ri) {
        float inv = 1.0f / lsum[ri];
        float4 o4 = make_float4(acc[ri][0] * inv, acc[ri][1] * inv,
                                acc[ri][2] * inv, acc[ri][3] * inv);
        *(float4*)&ctx[hoff + (size_t)(qt * 64 + ty * 4 + ri) * 1024 + tx * 4] = o4;
    }
}

// ---------------------------------------------------------------------------
// SwiGLU gate: u = silu(a) * b
// ---------------------------------------------------------------------------
__global__ void silu_mul_kernel(const float* __restrict__ a,
                                const float* __restrict__ b,
                                float* __restrict__ u, int n) {
    int i = blockIdx.x * blockDim.x + threadIdx.x;
    if (i < n) {
        float x = a[i];
        u[i] = (x / (1.0f + __expf(-x))) * b[i];
    }
}

// ---------------------------------------------------------------------------
// Launch
// ---------------------------------------------------------------------------
extern "C" void kernel_launch(void* const* d_in, const int* in_sizes, int n_in,
                              void* d_out, int out_size) {
    const float* x  = (const float*)d_in[0];
    const float* g1 = (const float*)d_in[1];
    const float* Wq = (const float*)d_in[2];
    const float* Wk = (const float*)d_in[3];
    const float* Wv = (const float*)d_in[4];
    const float* Wo = (const float*)d_in[5];
    const float* g2 = (const float*)d_in[6];
    const float* W1 = (const float*)d_in[7];
    const float* W2 = (const float*)d_in[8];
    const float* W3 = (const float*)d_in[9];
    float* out = (float*)d_out;

    float *h, *qq, *kk, *vv, *ctx, *x1, *h2, *fa, *fb;
    cudaGetSymbolAddress((void**)&h,   g_h);
    cudaGetSymbolAddress((void**)&qq,  g_q);
    cudaGetSymbolAddress((void**)&kk,  g_k);
    cudaGetSymbolAddress((void**)&vv,  g_v);
    cudaGetSymbolAddress((void**)&ctx, g_ctx);
    cudaGetSymbolAddress((void**)&x1,  g_x1);
    cudaGetSymbolAddress((void**)&h2,  g_h2);
    cudaGetSymbolAddress((void**)&fa,  g_fa);
    cudaGetSymbolAddress((void**)&fb,  g_fb);

    cudaFuncSetAttribute(attn_kernel,
                         cudaFuncAttributeMaxDynamicSharedMemorySize, ATT_SMEM);

    dim3 g8(8, 32);    // N=1024 GEMMs
    dim3 g22(22, 32);  // N=2730 GEMMs

    // h = rmsnorm(x, g1)
    rmsnorm_kernel<<<Mn, 256>>>(x, g1, h);
    // q, k, v projections
    gemm_kernel<0><<<g8, 256>>>(h, Wq, nullptr, qq, Mn, 1024, 1024);
    gemm_kernel<0><<<g8, 256>>>(h, Wk, nullptr, kk, Mn, 1024, 1024);
    gemm_kernel<0><<<g8, 256>>>(h, Wv, nullptr, vv, Mn, 1024, 1024);
    // causal attention
    attn_kernel<<<dim3(Tn / 64, Bn * Hn), 256, ATT_SMEM>>>(qq, kk, vv, ctx);
    // x1 = x + ctx @ Wo
    gemm_kernel<1><<<g8, 256>>>(ctx, Wo, x, x1, Mn, 1024, 1024);
    // h2 = rmsnorm(x1, g2)
    rmsnorm_kernel<<<Mn, 256>>>(x1, g2, h2);
    // SwiGLU MLP
    gemm_kernel<0><<<g22, 256>>>(h2, W1, nullptr, fa, Mn, DFFn, 1024);
    gemm_kernel<0><<<g22, 256>>>(h2, W2, nullptr, fb, Mn, DFFn, 1024);
    silu_mul_kernel<<<(Mn * DFFn + 255) / 256, 256>>>(fa, fb, fa, Mn * DFFn);
    // out = x1 + u @ W3
    gemm_kernel<1><<<g8, 256>>>(fa, W3, x1, out, Mn, 1024, DFFn);
}

// round 2
// speedup vs baseline: 1.2118x; 1.2118x over previous
#include <cuda_runtime.h>
#include <math.h>

// Problem constants
#define Bn   2
#define Tn   2048
#define Dn   1024
#define Hn   16
#define DHn  64
#define DFFn 2730
#define Mn   (Bn*Tn)          // 4096 rows
#define EPSn 1e-5f

typedef unsigned long long u64;

// ---------------------------------------------------------------------------
// Packed fp32x2 helpers (sm_100+ FFMA2 path — 2x fp32 FMA per instruction)
// ---------------------------------------------------------------------------
__device__ __forceinline__ void fma2(u64 &acc, u64 a, u64 b) {
    asm("fma.rn.f32x2 %0, %1, %2, %0;" : "+l"(acc) : "l"(a), "l"(b));
}
__device__ __forceinline__ u64 pack2(float lo, float hi) {
    u64 r; asm("mov.b64 %0, {%1, %2};" : "=l"(r) : "f"(lo), "f"(hi)); return r;
}
__device__ __forceinline__ float2 unpack2(u64 v) {
    float2 f; asm("mov.b64 {%0, %1}, %2;" : "=f"(f.x), "=f"(f.y) : "l"(v)); return f;
}
__device__ __forceinline__ u64 add2(u64 a, u64 b) {
    u64 r; asm("add.rn.f32x2 %0, %1, %2;" : "=l"(r) : "l"(a), "l"(b)); return r;
}
__device__ __forceinline__ u64 mul2(u64 a, u64 b) {
    u64 r; asm("mul.rn.f32x2 %0, %1, %2;" : "=l"(r) : "l"(a), "l"(b)); return r;
}

// ---------------------------------------------------------------------------
// Scratch (device globals — no dynamic allocation allowed)
// ---------------------------------------------------------------------------
__device__ float g_h  [Mn*Dn];        // rmsnorm(x)
__device__ float g_q  [Mn*Hn*DHn];
__device__ float g_k  [Mn*Hn*DHn];
__device__ float g_v  [Mn*Hn*DHn];
__device__ float g_ctx[Mn*Hn*DHn];
__device__ float g_x1 [Mn*Dn];        // x + ctx@Wo
__device__ float g_h2 [Mn*Dn];        // rmsnorm(x1)
__device__ float g_fa [Mn*DFFn];      // silu(h2@W1) * (h2@W2)
__device__ float g_fb [Mn*DFFn];      // h2@W2

// ---------------------------------------------------------------------------
// RMSNorm: one block per row, 256 threads, D=1024 → one float4 per thread
// ---------------------------------------------------------------------------
__global__ void rmsnorm_kernel(const float* __restrict__ x,
                               const float* __restrict__ g,
                               float* __restrict__ out) {
    const int row = blockIdx.x;
    const int t   = threadIdx.x;
    const float4* xr = (const float4*)(x + (size_t)row * Dn);
    float4 xv = xr[t];
    float ss = xv.x*xv.x + xv.y*xv.y + xv.z*xv.z + xv.w*xv.w;
    #pragma unroll
    for (int o = 16; o > 0; o >>= 1)
        ss += __shfl_xor_sync(0xffffffffu, ss, o);
    __shared__ float red[8];
    if ((t & 31) == 0) red[t >> 5] = ss;
    __syncthreads();
    float tot = red[0] + red[1] + red[2] + red[3] + red[4] + red[5] + red[6] + red[7];
    float rs = rsqrtf(tot * (1.0f / Dn) + EPSn);
    float4 gv = ((const float4*)g)[t];
    float4 o4 = make_float4(gv.x * xv.x * rs, gv.y * xv.y * rs,
                            gv.z * xv.z * rs, gv.w * xv.w * rs);
    ((float4*)(out + (size_t)row * Dn))[t] = o4;
}

// ---------------------------------------------------------------------------
// GEMM: C[M,N] = A[M,K] @ B[K,N], row-major. f32x2-packed inner loop.
// MODE 0: C = AB    MODE 1: C = AB + Res    MODE 2: C = silu(AB) * Res
// 128x128 tile, K-step 16, 256 threads, 8(row) x 4(col-pair) per thread.
// ---------------------------------------------------------------------------
#define KSTEP 16

template<int MODE>
__global__ void __launch_bounds__(256, 2)
gemm_kernel(const float* __restrict__ A,
            const float* __restrict__ Bm,
            const float* __restrict__ Res,
            float* __restrict__ C,
            int M, int N, int K) {
    __shared__ __align__(16) float As[KSTEP * 132];   // [k][row], padded
    __shared__ __align__(16) float Bs[KSTEP * 128];   // [k][col]
    const int tid = threadIdx.x;
    const int tx = tid & 15, ty = tid >> 4;
    const int rowBase = blockIdx.y * 128;
    const int colBase = blockIdx.x * 128;

    u64 acc[8][4];
    #pragma unroll
    for (int i = 0; i < 8; ++i)
        #pragma unroll
        for (int jp = 0; jp < 4; ++jp) acc[i][jp] = 0ull;

    const int numK = (K + KSTEP - 1) / KSTEP;
    for (int kt = 0; kt < numK; ++kt) {
        const int k0 = kt * KSTEP;
        #pragma unroll
        for (int l = 0; l < 8; ++l) {              // A tile: 128 rows x 16 k
            int idx = tid + (l << 8);
            int r = idx >> 4, kk = idx & 15;
            float val = (k0 + kk < K) ? A[(size_t)(rowBase + r) * K + k0 + kk] : 0.0f;
            As[kk * 132 + r] = val;
        }
        #pragma unroll
        for (int l = 0; l < 8; ++l) {              // B tile: 16 k x 128 cols
            int idx = tid + (l << 8);
            int kk = idx >> 7, cc = idx & 127;
            int col = colBase + cc;
            float val = (k0 + kk < K && col < N) ? Bm[(size_t)(k0 + kk) * N + col] : 0.0f;
            Bs[kk * 128 + cc] = val;
        }
        __syncthreads();
        #pragma unroll
        for (int kk = 0; kk < KSTEP; ++kk) {
            float4 a0 = *(const float4*)&As[kk * 132 + ty * 8];
            float4 a1 = *(const float4*)&As[kk * 132 + ty * 8 + 4];
            const u64* bp = (const u64*)&Bs[kk * 128 + tx * 8];
            u64 b2[4] = {bp[0], bp[1], bp[2], bp[3]};
            float av[8] = {a0.x, a0.y, a0.z, a0.w, a1.x, a1.y, a1.z, a1.w};
            #pragma unroll
            for (int i = 0; i < 8; ++i) {
                u64 a2 = pack2(av[i], av[i]);
                #pragma unroll
                for (int jp = 0; jp < 4; ++jp)
                    fma2(acc[i][jp], a2, b2[jp]);
            }
        }
        __syncthreads();
    }
    #pragma unroll
    for (int i = 0; i < 8; ++i) {
        int row = rowBase + ty * 8 + i;
        #pragma unroll
        for (int jp = 0; jp < 4; ++jp) {
            int col = colBase + tx * 8 + jp * 2;
            if (col < N) {                          // N even → pair never straddles
                u64 r = acc[i][jp];
                if (MODE == 1) {
                    u64 res = *(const u64*)&Res[(size_t)row * N + col];
                    r = add2(r, res);
                } else if (MODE == 2) {
                    float2 v = unpack2(r);
                    float2 g = *(const float2*)&Res[(size_t)row * N + col];
                    v.x = v.x / (1.0f + __expf(-v.x)) * g.x;
                    v.y = v.y / (1.0f + __expf(-v.y)) * g.y;
                    r = pack2(v.x, v.y);
                }
                *(u64*)&C[(size_t)row * N + col] = r;
            }
        }
    }
}

// ---------------------------------------------------------------------------
// Flash attention, causal, scale 0.125. ALiBi bias is identically zero on the
// causal region (dist = clip(j-i,0) == 0 for j<=i), so omitted.
// f32x2-packed QK^T (packed along d) and PV (packed along output dim).
// ---------------------------------------------------------------------------
#define ATT_STRIDE 68           // 64 + 4 pad
#define ATT_SMEM   (4 * 64 * ATT_STRIDE * 4)   // Qs,Ks,Vs,Ss = 69632 bytes

__global__ void attn_kernel(const float* __restrict__ q,
                            const float* __restrict__ k,
                            const float* __restrict__ v,
                            float* __restrict__ ctx) {
    extern __shared__ float sm[];
    float* Qs = sm;
    float* Ks = sm + 64 * ATT_STRIDE;
    float* Vs = sm + 2 * 64 * ATT_STRIDE;
    float* Ss = sm + 3 * 64 * ATT_STRIDE;

    const int qt = blockIdx.x;
    const int bh = blockIdx.y;
    const int b = bh >> 4, h = bh & 15;
    const int tid = threadIdx.x;
    const int tx = tid & 15, ty = tid >> 4;
    const size_t hoff = (size_t)b * Tn * 1024 + (size_t)h * 64;

    #pragma unroll
    for (int l = 0; l < 16; ++l) {
        int idx = tid + (l << 8);
        int j = idx >> 6, d = idx & 63;
        Qs[j * ATT_STRIDE + d] = q[hoff + (size_t)(qt * 64 + j) * 1024 + d] * 0.125f;
    }

    float m[4], lsum[4];
    u64 acc2[4][2];                 // 4 rows x 4 dims (2 pairs)
    #pragma unroll
    for (int ri = 0; ri < 4; ++ri) {
        m[ri] = -1e30f; lsum[ri] = 0.0f;
        acc2[ri][0] = 0ull; acc2[ri][1] = 0ull;
    }
    __syncthreads();

    for (int kt = 0; kt <= qt; ++kt) {
        #pragma unroll
        for (int l = 0; l < 16; ++l) {
            int idx = tid + (l << 8);
            int j = idx >> 6, d = idx & 63;
            size_t g = hoff + (size_t)(kt * 64 + j) * 1024 + d;
            Ks[j * ATT_STRIDE + d] = k[g];
            Vs[j * ATT_STRIDE + d] = v[g];
        }
        __syncthreads();

        // S = Q K^T, packed along d: s2 lanes hold (even-d, odd-d) partials
        u64 s2[4][4];
        #pragma unroll
        for (int ri = 0; ri < 4; ++ri)
            #pragma unroll
            for (int ji = 0; ji < 4; ++ji) s2[ri][ji] = 0ull;

        #pragma unroll 4
        for (int d = 0; d < 64; d += 4) {
            u64 q2[4][2], k2[4][2];
            #pragma unroll
            for (int ri = 0; ri < 4; ++ri) {
                const u64* qp = (const u64*)&Qs[(ty * 4 + ri) * ATT_STRIDE + d];
                q2[ri][0] = qp[0]; q2[ri][1] = qp[1];
            }
            #pragma unroll
            for (int ji = 0; ji < 4; ++ji) {
                const u64* kp = (const u64*)&Ks[(tx * 4 + ji) * ATT_STRIDE + d];
                k2[ji][0] = kp[0]; k2[ji][1] = kp[1];
            }
            #pragma unroll
            for (int ri = 0; ri < 4; ++ri)
                #pragma unroll
                for (int ji = 0; ji < 4; ++ji) {
                    fma2(s2[ri][ji], q2[ri][0], k2[ji][0]);
                    fma2(s2[ri][ji], q2[ri][1], k2[ji][1]);
                }
        }
        float s[4][4];
        #pragma unroll
        for (int ri = 0; ri < 4; ++ri)
            #pragma unroll
            for (int ji = 0; ji < 4; ++ji) {
                float2 f = unpack2(s2[ri][ji]);
                s[ri][ji] = f.x + f.y;
            }

        if (kt == qt) {    // causal mask on diagonal tile only
            #pragma unroll
            for (int ri = 0; ri < 4; ++ri)
                #pragma unroll
                for (int ji = 0; ji < 4; ++ji)
                    if (tx * 4 + ji > ty * 4 + ri) s[ri][ji] = -1e30f;
        }

        // Online softmax per row
        #pragma unroll
        for (int ri = 0; ri < 4; ++ri) {
            float mx = fmaxf(fmaxf(s[ri][0], s[ri][1]), fmaxf(s[ri][2], s[ri][3]));
            #pragma unroll
            for (int o = 8; o > 0; o >>= 1)
                mx = fmaxf(mx, __shfl_xor_sync(0xffffffffu, mx, o));
            float mnew = fmaxf(m[ri], mx);
            float ps = __expf(m[ri] - mnew);
            m[ri] = mnew;
            float ls = 0.0f;
            #pragma unroll
            for (int ji = 0; ji < 4; ++ji) {
                float p = __expf(s[ri][ji] - mnew);
                s[ri][ji] = p;
                ls += p;
            }
            #pragma unroll
            for (int o = 8; o > 0; o >>= 1)
                ls += __shfl_xor_sync(0xffffffffu, ls, o);
            lsum[ri] = lsum[ri] * ps + ls;
            u64 ps2 = pack2(ps, ps);
            acc2[ri][0] = mul2(acc2[ri][0], ps2);
            acc2[ri][1] = mul2(acc2[ri][1], ps2);
            #pragma unroll
            for (int ji = 0; ji < 4; ++ji)
                Ss[(ty * 4 + ri) * ATT_STRIDE + tx * 4 + ji] = s[ri][ji];
        }
        __syncthreads();

        // O += P V, packed along output dim
        #pragma unroll 4
        for (int j = 0; j < 64; j += 4) {
            float4 pr[4];
            #pragma unroll
            for (int ri = 0; ri < 4; ++ri)
                pr[ri] = *(const float4*)&Ss[(ty * 4 + ri) * ATT_STRIDE + j];
            float pa[4][4];
            #pragma unroll
            for (int ri = 0; ri < 4; ++ri) {
                pa[ri][0] = pr[ri].x; pa[ri][1] = pr[ri].y;
                pa[ri][2] = pr[ri].z; pa[ri][3] = pr[ri].w;
            }
            #pragma unroll
            for (int jj = 0; jj < 4; ++jj) {
                const u64* vp = (const u64*)&Vs[(j + jj) * ATT_STRIDE + tx * 4];
                u64 v0 = vp[0], v1 = vp[1];
                #pragma unroll
                for (int ri = 0; ri < 4; ++ri) {
                    u64 p2 = pack2(pa[ri][jj], pa[ri][jj]);
                    fma2(acc2[ri][0], p2, v0);
                    fma2(acc2[ri][1], p2, v1);
                }
            }
        }
        __syncthreads();
    }

    #pragma unroll
    for (int ri = 0; ri < 4; ++ri) {
        float inv = 1.0f / lsum[ri];
        float2 d01 = unpack2(acc2[ri][0]);
        float2 d23 = unpack2(acc2[ri][1]);
        float4 o4 = make_float4(d01.x * inv, d01.y * inv, d23.x * inv, d23.y * inv);
        *(float4*)&ctx[hoff + (size_t)(qt * 64 + ty * 4 + ri) * 1024 + tx * 4] = o4;
    }
}

// ---------------------------------------------------------------------------
// Launch
// ---------------------------------------------------------------------------
extern "C" void kernel_launch(void* const* d_in, const int* in_sizes, int n_in,
                              void* d_out, int out_size) {
    const float* x  = (const float*)d_in[0];
    const float* g1 = (const float*)d_in[1];
    const float* Wq = (const float*)d_in[2];
    const float* Wk = (const float*)d_in[3];
    const float* Wv = (const float*)d_in[4];
    const float* Wo = (const float*)d_in[5];
    const float* g2 = (const float*)d_in[6];
    const float* W1 = (const float*)d_in[7];
    const float* W2 = (const float*)d_in[8];
    const float* W3 = (const float*)d_in[9];
    float* out = (float*)d_out;

    float *h, *qq, *kk, *vv, *ctx, *x1, *h2, *fa, *fb;
    cudaGetSymbolAddress((void**)&h,   g_h);
    cudaGetSymbolAddress((void**)&qq,  g_q);
    cudaGetSymbolAddress((void**)&kk,  g_k);
    cudaGetSymbolAddress((void**)&vv,  g_v);
    cudaGetSymbolAddress((void**)&ctx, g_ctx);
    cudaGetSymbolAddress((void**)&x1,  g_x1);
    cudaGetSymbolAddress((void**)&h2,  g_h2);
    cudaGetSymbolAddress((void**)&fa,  g_fa);
    cudaGetSymbolAddress((void**)&fb,  g_fb);

    cudaFuncSetAttribute(attn_kernel,
                         cudaFuncAttributeMaxDynamicSharedMemorySize, ATT_SMEM);

    dim3 g8(8, 32);    // N=1024 GEMMs
    dim3 g22(22, 32);  // N=2730 GEMMs

    // h = rmsnorm(x, g1)
    rmsnorm_kernel<<<Mn, 256>>>(x, g1, h);
    // q, k, v projections
    gemm_kernel<0><<<g8, 256>>>(h, Wq, nullptr, qq, Mn, 1024, 1024);
    gemm_kernel<0><<<g8, 256>>>(h, Wk, nullptr, kk, Mn, 1024, 1024);
    gemm_kernel<0><<<g8, 256>>>(h, Wv, nullptr, vv, Mn, 1024, 1024);
    // causal attention
    attn_kernel<<<dim3(Tn / 64, Bn * Hn), 256, ATT_SMEM>>>(qq, kk, vv, ctx);
    // x1 = x + ctx @ Wo
    gemm_kernel<1><<<g8, 256>>>(ctx, Wo, x, x1, Mn, 1024, 1024);
    // h2 = rmsnorm(x1, g2)
    rmsnorm_kernel<<<Mn, 256>>>(x1, g2, h2);
    // SwiGLU MLP: fb = h2@W2; fa = silu(h2@W1) * fb  (gate fused in epilogue)
    gemm_kernel<0><<<g22, 256>>>(h2, W2, nullptr, fb, Mn, DFFn, 1024);
    gemm_kernel<2><<<g22, 256>>>(h2, W1, fb, fa, Mn, DFFn, 1024);
    // out = x1 + fa @ W3
    gemm_kernel<1><<<g8, 256>>>(fa, W3, x1, out, Mn, 1024, DFFn);
}

// round 5
// speedup vs baseline: 1.9140x; 1.5795x over previous
#include <cuda_runtime.h>
#include <cuda_bf16.h>
#include <math.h>
#include <stdint.h>

// Problem constants
#define Bn   2
#define Tn   2048
#define Dn   1024
#define Hn   16
#define DHn  64
#define DFFn 2730
#define Mn   (Bn*Tn)          // 4096 rows
#define EPSn 1e-5f
#define DFFp 2816             // padded N for W1/W2 (22*128)
#define KFp  2752             // padded K for fa / W3 (86*32)

typedef unsigned long long u64;

// ---------------------------------------------------------------------------
// f32x2 helpers (attention kernel)
// ---------------------------------------------------------------------------
__device__ __forceinline__ void fma2(u64 &acc, u64 a, u64 b) {
    asm("fma.rn.f32x2 %0, %1, %2, %0;" : "+l"(acc) : "l"(a), "l"(b));
}
__device__ __forceinline__ u64 pack2(float lo, float hi) {
    u64 r; asm("mov.b64 %0, {%1, %2};" : "=l"(r) : "f"(lo), "f"(hi)); return r;
}
__device__ __forceinline__ float2 unpack2(u64 v) {
    float2 f; asm("mov.b64 {%0, %1}, %2;" : "=f"(f.x), "=f"(f.y) : "l"(v)); return f;
}
__device__ __forceinline__ u64 mul2(u64 a, u64 b) {
    u64 r; asm("mul.rn.f32x2 %0, %1, %2;" : "=l"(r) : "l"(a), "l"(b)); return r;
}

__device__ __forceinline__ uint32_t smem_u32(const void* p) {
    uint32_t a;
    asm("{ .reg .u64 t; cvta.to.shared.u64 t, %1; cvt.u32.u64 %0, t; }"
        : "=r"(a) : "l"(p));
    return a;
}

// ---------------------------------------------------------------------------
// Scratch (device globals)
// ---------------------------------------------------------------------------
__device__ float g_q  [Mn*Dn];
__device__ float g_k  [Mn*Dn];
__device__ float g_v  [Mn*Dn];
__device__ float g_ctx[Mn*Dn];
__device__ float g_x1 [Mn*Dn];
__device__ float g_fb [Mn*DFFn];

__device__ __nv_bfloat16 g_hh [Mn*Dn], g_hl [Mn*Dn];
__device__ __nv_bfloat16 g_h2h[Mn*Dn], g_h2l[Mn*Dn];
__device__ __nv_bfloat16 g_cxh[Mn*Dn], g_cxl[Mn*Dn];
__device__ __nv_bfloat16 g_fah[(size_t)Mn*KFp], g_fal[(size_t)Mn*KFp];
__device__ __nv_bfloat16 g_Wqh[Dn*Dn],  g_Wql[Dn*Dn];
__device__ __nv_bfloat16 g_Wkh[Dn*Dn],  g_Wkl[Dn*Dn];
__device__ __nv_bfloat16 g_Wvh[Dn*Dn],  g_Wvl[Dn*Dn];
__device__ __nv_bfloat16 g_Woh[Dn*Dn],  g_Wol[Dn*Dn];
__device__ __nv_bfloat16 g_W1h[(size_t)DFFp*Dn], g_W1l[(size_t)DFFp*Dn];
__device__ __nv_bfloat16 g_W2h[(size_t)DFFp*Dn], g_W2l[(size_t)DFFp*Dn];
__device__ __nv_bfloat16 g_W3h[(size_t)Dn*KFp],  g_W3l[(size_t)Dn*KFp];

// ---------------------------------------------------------------------------
// RMSNorm with bf16 hi/lo split output
// ---------------------------------------------------------------------------
__device__ __forceinline__ uint32_t pack_bf2(__nv_bfloat16 a, __nv_bfloat16 b) {
    return ((uint32_t)__bfloat16_as_ushort(b) << 16) | __bfloat16_as_ushort(a);
}
__global__ void rmsnorm_split_kernel(const float* __restrict__ x,
                                     const float* __restrict__ g,
                                     __nv_bfloat16* __restrict__ oh,
                                     __nv_bfloat16* __restrict__ ol) {
    const int row = blockIdx.x;
    const int t   = threadIdx.x;
    const float4* xr = (const float4*)(x + (size_t)row * Dn);
    float4 xv = xr[t];
    float ss = xv.x*xv.x + xv.y*xv.y + xv.z*xv.z + xv.w*xv.w;
    #pragma unroll
    for (int o = 16; o > 0; o >>= 1) ss += __shfl_xor_sync(0xffffffffu, ss, o);
    __shared__ float red[8];
    if ((t & 31) == 0) red[t >> 5] = ss;
    __syncthreads();
    float tot = red[0]+red[1]+red[2]+red[3]+red[4]+red[5]+red[6]+red[7];
    float rs = rsqrtf(tot * (1.0f / Dn) + EPSn);
    float4 gv = ((const float4*)g)[t];
    float o0 = gv.x*xv.x*rs, o1 = gv.y*xv.y*rs, o2 = gv.z*xv.z*rs, o3 = gv.w*xv.w*rs;
    __nv_bfloat16 h0 = __float2bfloat16(o0), h1 = __float2bfloat16(o1);
    __nv_bfloat16 h2 = __float2bfloat16(o2), h3 = __float2bfloat16(o3);
    __nv_bfloat16 l0 = __float2bfloat16(o0 - __bfloat162float(h0));
    __nv_bfloat16 l1 = __float2bfloat16(o1 - __bfloat162float(h1));
    __nv_bfloat16 l2 = __float2bfloat16(o2 - __bfloat162float(h2));
    __nv_bfloat16 l3 = __float2bfloat16(o3 - __bfloat162float(h3));
    uint2 uh = make_uint2(pack_bf2(h0,h1), pack_bf2(h2,h3));
    uint2 ul = make_uint2(pack_bf2(l0,l1), pack_bf2(l2,l3));
    *(uint2*)&oh[(size_t)row*Dn + t*4] = uh;
    *(uint2*)&ol[(size_t)row*Dn + t*4] = ul;
}

// ---------------------------------------------------------------------------
// Elementwise fp32 -> bf16 hi/lo split (for ctx)
// ---------------------------------------------------------------------------
__global__ void split_kernel(const float* __restrict__ in,
                             __nv_bfloat16* __restrict__ oh,
                             __nv_bfloat16* __restrict__ ol, int n4) {
    int i = blockIdx.x * blockDim.x + threadIdx.x;
    if (i >= n4) return;
    float4 v = ((const float4*)in)[i];
    __nv_bfloat16 h0=__float2bfloat16(v.x), h1=__float2bfloat16(v.y);
    __nv_bfloat16 h2=__float2bfloat16(v.z), h3=__float2bfloat16(v.w);
    __nv_bfloat16 l0=__float2bfloat16(v.x-__bfloat162float(h0));
    __nv_bfloat16 l1=__float2bfloat16(v.y-__bfloat162float(h1));
    __nv_bfloat16 l2=__float2bfloat16(v.z-__bfloat162float(h2));
    __nv_bfloat16 l3=__float2bfloat16(v.w-__bfloat162float(h3));
    ((uint2*)oh)[i] = make_uint2(pack_bf2(h0,h1), pack_bf2(h2,h3));
    ((uint2*)ol)[i] = make_uint2(pack_bf2(l0,l1), pack_bf2(l2,l3));
}

// ---------------------------------------------------------------------------
// Weight transpose + split: W[K,N] fp32 -> Wt_hi/lo [Np, Kp] bf16 (zero-pad)
// ---------------------------------------------------------------------------
__global__ void transpose_split_kernel(const float* __restrict__ W,
                                       __nv_bfloat16* __restrict__ Th,
                                       __nv_bfloat16* __restrict__ Tl,
                                       int K, int N, int Kp, int Np) {
    __shared__ float tile[32][33];
    int kb = blockIdx.x * 32, nb = blockIdx.y * 32;
    int tx = threadIdx.x, ty = threadIdx.y;   // 32 x 8
    #pragma unroll
    for (int i = 0; i < 32; i += 8) {
        int k = kb + ty + i, n = nb + tx;
        tile[ty + i][tx] = (k < K && n < N) ? W[(size_t)k * N + n] : 0.0f;
    }
    __syncthreads();
    #pragma unroll
    for (int i = 0; i < 32; i += 8) {
        int n = nb + ty + i, k = kb + tx;
        if (n < Np && k < Kp) {
            float v = tile[tx][ty + i];
            __nv_bfloat16 h = __float2bfloat16(v);
            Th[(size_t)n * Kp + k] = h;
            Tl[(size_t)n * Kp + k] = __float2bfloat16(v - __bfloat162float(h));
        }
    }
}

// ---------------------------------------------------------------------------
// HMMA split-bf16 GEMM: D[M,N] = (Ah+Al)[M,K] @ (Bh+Bl)^T, Bt = [N,K] bf16.
// 3 passes (AhBh, AhBl, AlBh), fp32 accumulators.
// Tile 128x128, 8 warps (2Mx4N), warp tile 64x32, mma.m16n8k16.
// K-chunk 32, cp.async double-buffered smem, 80B row stride (conflict-free).
// MODE 0: Out = D   MODE 1: Out = D + Res   MODE 2: Oh/Ol = split(silu(D)*Res)
// ---------------------------------------------------------------------------
#define ROWB 80   // bytes per 32-bf16 smem row (64B data + 16B pad)

__device__ __forceinline__ void cp16(uint32_t d, const void* s) {
    asm volatile("cp.async.cg.shared.global [%0], [%1], 16;"
                 :: "r"(d), "l"(s) : "memory");
}

template<int MODE>
__global__ void __launch_bounds__(256, 2)
mma_gemm(const __nv_bfloat16* __restrict__ Ah, const __nv_bfloat16* __restrict__ Al,
         const __nv_bfloat16* __restrict__ Bh, const __nv_bfloat16* __restrict__ Bl,
         const float* __restrict__ Res, float* __restrict__ Out,
         __nv_bfloat16* __restrict__ Oh, __nv_bfloat16* __restrict__ Ol,
         int K, int Nout, int resN, int resStride, int outStride) {
    __shared__ __align__(16) char Asm[2][128 * ROWB];
    __shared__ __align__(16) char Bsm[2][128 * ROWB];

    const int tid  = threadIdx.x;
    const int wid  = tid >> 5, lane = tid & 31;
    const int wM = (wid >> 2) * 64, wN = (wid & 3) * 32;
    const int rowBase = blockIdx.y * 128;
    const int colBase = blockIdx.x * 128;

    float acc[4][4][4];
    #pragma unroll
    for (int mi = 0; mi < 4; ++mi)
        #pragma unroll
        for (int ni = 0; ni < 4; ++ni)
            #pragma unroll
            for (int e = 0; e < 4; ++e) acc[mi][ni][e] = 0.0f;

    const int cpp = K >> 5;        // chunks per pass
    const int nch = 3 * cpp;

    // issue chunk c's loads
    auto issue = [&](int c) {
        const int pass = c / cpp;
        const int k0 = (c - pass * cpp) << 5;
        const __nv_bfloat16* As = (pass == 2) ? Al : Ah;
        const __nv_bfloat16* Bs = (pass == 1) ? Bl : Bh;
        char* ab = Asm[c & 1];
        char* bb = Bsm[c & 1];
        #pragma unroll
        for (int l = 0; l < 2; ++l) {
            int idx = tid + (l << 8);          // 0..511
            int row = idx >> 2, ch = idx & 3;
            uint32_t so = (uint32_t)(row * ROWB + ch * 16);
            cp16(smem_u32(ab + so), As + (size_t)(rowBase + row) * K + k0 + ch * 8);
            cp16(smem_u32(bb + so), Bs + (size_t)(colBase + row) * K + k0 + ch * 8);
        }
        asm volatile("cp.async.commit_group;" ::: "memory");
    };

    issue(0);
    for (int c = 0; c < nch; ++c) {
        if (c + 1 < nch) {
            issue(c + 1);
            asm volatile("cp.async.wait_group 1;" ::: "memory");
        } else {
            asm volatile("cp.async.wait_group 0;" ::: "memory");
        }
        __syncthreads();

        const char* ab = Asm[c & 1];
        const char* bb = Bsm[c & 1];
        #pragma unroll
        for (int ks = 0; ks < 2; ++ks) {
            uint32_t a[4][4], b[4][2];
            #pragma unroll
            for (int mi = 0; mi < 4; ++mi) {
                uint32_t ad = smem_u32(ab + (wM + mi * 16 + (lane & 15)) * ROWB
                                          + ks * 32 + ((lane >> 4) & 1) * 16);
                asm volatile("ldmatrix.sync.aligned.m8n8.x4.shared.b16 "
                             "{%0,%1,%2,%3}, [%4];"
                             : "=r"(a[mi][0]), "=r"(a[mi][1]),
                               "=r"(a[mi][2]), "=r"(a[mi][3]) : "r"(ad));
            }
            #pragma unroll
            for (int ni = 0; ni < 4; ++ni) {
                uint32_t bd = smem_u32(bb + (wN + ni * 8 + (lane & 7)) * ROWB
                                          + ks * 32 + ((lane >> 3) & 1) * 16);
                asm volatile("ldmatrix.sync.aligned.m8n8.x2.shared.b16 "
                             "{%0,%1}, [%2];"
                             : "=r"(b[ni][0]), "=r"(b[ni][1]) : "r"(bd));
            }
            #pragma unroll
            for (int mi = 0; mi < 4; ++mi)
                #pragma unroll
                for (int ni = 0; ni < 4; ++ni)
                    asm volatile(
                        "mma.sync.aligned.m16n8k16.row.col.f32.bf16.bf16.f32 "
                        "{%0,%1,%2,%3}, {%4,%5,%6,%7}, {%8,%9}, {%0,%1,%2,%3};"
                        : "+f"(acc[mi][ni][0]), "+f"(acc[mi][ni][1]),
                          "+f"(acc[mi][ni][2]), "+f"(acc[mi][ni][3])
                        : "r"(a[mi][0]), "r"(a[mi][1]), "r"(a[mi][2]), "r"(a[mi][3]),
                          "r"(b[ni][0]), "r"(b[ni][1]));
        }
        __syncthreads();
    }

    // Epilogue: thread holds C[r][c],C[r][c+1] (c0,c1) and C[r+8][...] (c2,c3)
    #pragma unroll
    for (int mi = 0; mi < 4; ++mi) {
        #pragma unroll
        for (int ni = 0; ni < 4; ++ni) {
            int col = colBase + wN + ni * 8 + (lane & 3) * 2;
            if (col >= Nout) continue;
            int r0 = rowBase + wM + mi * 16 + (lane >> 2);
            #pragma unroll
            for (int half = 0; half < 2; ++half) {
                int row = r0 + half * 8;
                float v0 = acc[mi][ni][half * 2];
                float v1 = acc[mi][ni][half * 2 + 1];
                if (MODE == 1) {
                    float2 r = *(const float2*)&Res[(size_t)row * resStride + col];
                    v0 += r.x; v1 += r.y;
                    *(float2*)&Out[(size_t)row * outStride + col] = make_float2(v0, v1);
                } else if (MODE == 2) {
                    float r0v = 0.0f, r1v = 0.0f;
                    if (col < resN) {
                        float2 r = *(const float2*)&Res[(size_t)row * resStride + col];
                        r0v = r.x; r1v = r.y;
                    }
                    v0 = v0 / (1.0f + __expf(-v0)) * r0v;
                    v1 = v1 / (1.0f + __expf(-v1)) * r1v;
                    __nv_bfloat16 h0 = __float2bfloat16(v0), h1 = __float2bfloat16(v1);
                    __nv_bfloat16 l0 = __float2bfloat16(v0 - __bfloat162float(h0));
                    __nv_bfloat16 l1 = __float2bfloat16(v1 - __bfloat162float(h1));
                    *(uint32_t*)&Oh[(size_t)row * outStride + col] = pack_bf2(h0, h1);
                    *(uint32_t*)&Ol[(size_t)row * outStride + col] = pack_bf2(l0, l1);
                } else {
                    *(float2*)&Out[(size_t)row * outStride + col] = make_float2(v0, v1);
                }
            }
        }
    }
}

// ---------------------------------------------------------------------------
// Flash attention (round-2 version, passing): causal, scale 0.125, ALiBi = 0
// on causal region. f32x2-packed.
// ---------------------------------------------------------------------------
#define ATT_STRIDE 68
#define ATT_SMEM   (4 * 64 * ATT_STRIDE * 4)

__global__ void attn_kernel(const float* __restrict__ q,
                            const float* __restrict__ k,
                            const float* __restrict__ v,
                            float* __restrict__ ctx) {
    extern __shared__ float sm[];
    float* Qs = sm;
    float* Ks = sm + 64 * ATT_STRIDE;
    float* Vs = sm + 2 * 64 * ATT_STRIDE;
    float* Ss = sm + 3 * 64 * ATT_STRIDE;

    const int qt = blockIdx.x;
    const int bh = blockIdx.y;
    const int b = bh >> 4, h = bh & 15;
    const int tid = threadIdx.x;
    const int tx = tid & 15, ty = tid >> 4;
    const size_t hoff = (size_t)b * Tn * 1024 + (size_t)h * 64;

    #pragma unroll
    for (int l = 0; l < 16; ++l) {
        int idx = tid + (l << 8);
        int j = idx >> 6, d = idx & 63;
        Qs[j * ATT_STRIDE + d] = q[hoff + (size_t)(qt * 64 + j) * 1024 + d] * 0.125f;
    }

    float m[4], lsum[4];
    u64 acc2[4][2];
    #pragma unroll
    for (int ri = 0; ri < 4; ++ri) {
        m[ri] = -1e30f; lsum[ri] = 0.0f;
        acc2[ri][0] = 0ull; acc2[ri][1] = 0ull;
    }
    __syncthreads();

    for (int kt = 0; kt <= qt; ++kt) {
        #pragma unroll
        for (int l = 0; l < 16; ++l) {
            int idx = tid + (l << 8);
            int j = idx >> 6, d = idx & 63;
            size_t g = hoff + (size_t)(kt * 64 + j) * 1024 + d;
            Ks[j * ATT_STRIDE + d] = k[g];
            Vs[j * ATT_STRIDE + d] = v[g];
        }
        __syncthreads();

        u64 s2[4][4];
        #pragma unroll
        for (int ri = 0; ri < 4; ++ri)
            #pragma unroll
            for (int ji = 0; ji < 4; ++ji) s2[ri][ji] = 0ull;

        #pragma unroll 4
        for (int d = 0; d < 64; d += 4) {
            u64 q2[4][2], k2[4][2];
            #pragma unroll
            for (int ri = 0; ri < 4; ++ri) {
                const u64* qp = (const u64*)&Qs[(ty * 4 + ri) * ATT_STRIDE + d];
                q2[ri][0] = qp[0]; q2[ri][1] = qp[1];
            }
            #pragma unroll
            for (int ji = 0; ji < 4; ++ji) {
                const u64* kp = (const u64*)&Ks[(tx * 4 + ji) * ATT_STRIDE + d];
                k2[ji][0] = kp[0]; k2[ji][1] = kp[1];
            }
            #pragma unroll
            for (int ri = 0; ri < 4; ++ri)
                #pragma unroll
                for (int ji = 0; ji < 4; ++ji) {
                    fma2(s2[ri][ji], q2[ri][0], k2[ji][0]);
                    fma2(s2[ri][ji], q2[ri][1], k2[ji][1]);
                }
        }
        float s[4][4];
        #pragma unroll
        for (int ri = 0; ri < 4; ++ri)
            #pragma unroll
            for (int ji = 0; ji < 4; ++ji) {
                float2 f = unpack2(s2[ri][ji]);
                s[ri][ji] = f.x + f.y;
            }

        if (kt == qt) {
            #pragma unroll
            for (int ri = 0; ri < 4; ++ri)
                #pragma unroll
                for (int ji = 0; ji < 4; ++ji)
                    if (tx * 4 + ji > ty * 4 + ri) s[ri][ji] = -1e30f;
        }

        #pragma unroll
        for (int ri = 0; ri < 4; ++ri) {
            float mx = fmaxf(fmaxf(s[ri][0], s[ri][1]), fmaxf(s[ri][2], s[ri][3]));
            #pragma unroll
            for (int o = 8; o > 0; o >>= 1)
                mx = fmaxf(mx, __shfl_xor_sync(0xffffffffu, mx, o));
            float mnew = fmaxf(m[ri], mx);
            float ps = __expf(m[ri] - mnew);
            m[ri] = mnew;
            float ls = 0.0f;
            #pragma unroll
            for (int ji = 0; ji < 4; ++ji) {
                float p = __expf(s[ri][ji] - mnew);
                s[ri][ji] = p;
                ls += p;
            }
            #pragma unroll
            for (int o = 8; o > 0; o >>= 1)
                ls += __shfl_xor_sync(0xffffffffu, ls, o);
            lsum[ri] = lsum[ri] * ps + ls;
            u64 ps2 = pack2(ps, ps);
            acc2[ri][0] = mul2(acc2[ri][0], ps2);
            acc2[ri][1] = mul2(acc2[ri][1], ps2);
            #pragma unroll
            for (int ji = 0; ji < 4; ++ji)
                Ss[(ty * 4 + ri) * ATT_STRIDE + tx * 4 + ji] = s[ri][ji];
        }
        __syncthreads();

        #pragma unroll 4
        for (int j = 0; j < 64; j += 4) {
            float4 pr[4];
            #pragma unroll
            for (int ri = 0; ri < 4; ++ri)
                pr[ri] = *(const float4*)&Ss[(ty * 4 + ri) * ATT_STRIDE + j];
            float pa[4][4];
            #pragma unroll
            for (int ri = 0; ri < 4; ++ri) {
                pa[ri][0] = pr[ri].x; pa[ri][1] = pr[ri].y;
                pa[ri][2] = pr[ri].z; pa[ri][3] = pr[ri].w;
            }
            #pragma unroll
            for (int jj = 0; jj < 4; ++jj) {
                const u64* vp = (const u64*)&Vs[(j + jj) * ATT_STRIDE + tx * 4];
                u64 v0 = vp[0], v1 = vp[1];
                #pragma unroll
                for (int ri = 0; ri < 4; ++ri) {
                    u64 p2 = pack2(pa[ri][jj], pa[ri][jj]);
                    fma2(acc2[ri][0], p2, v0);
                    fma2(acc2[ri][1], p2, v1);
                }
            }
        }
        __syncthreads();
    }

    #pragma unroll
    for (int ri = 0; ri < 4; ++ri) {
        float inv = 1.0f / lsum[ri];
        float2 d01 = unpack2(acc2[ri][0]);
        float2 d23 = unpack2(acc2[ri][1]);
        float4 o4 = make_float4(d01.x * inv, d01.y * inv, d23.x * inv, d23.y * inv);
        *(float4*)&ctx[hoff + (size_t)(qt * 64 + ty * 4 + ri) * 1024 + tx * 4] = o4;
    }
}

// ---------------------------------------------------------------------------
// Launch
// ---------------------------------------------------------------------------
extern "C" void kernel_launch(void* const* d_in, const int* in_sizes, int n_in,
                              void* d_out, int out_size) {
    const float* x  = (const float*)d_in[0];
    const float* g1 = (const float*)d_in[1];
    const float* Wq = (const float*)d_in[2];
    const float* Wk = (const float*)d_in[3];
    const float* Wv = (const float*)d_in[4];
    const float* Wo = (const float*)d_in[5];
    const float* g2 = (const float*)d_in[6];
    const float* W1 = (const float*)d_in[7];
    const float* W2 = (const float*)d_in[8];
    const float* W3 = (const float*)d_in[9];
    float* out = (float*)d_out;

    float *q, *k, *v, *ctx, *x1, *fb;
    __nv_bfloat16 *hh,*hl,*h2h,*h2l,*cxh,*cxl,*fah,*fal;
    __nv_bfloat16 *Wqh,*Wql,*Wkh,*Wkl,*Wvh,*Wvl,*Woh,*Wol,*W1h,*W1l,*W2h,*W2l,*W3h,*W3l;
    cudaGetSymbolAddress((void**)&q,   g_q);
    cudaGetSymbolAddress((void**)&k,   g_k);
    cudaGetSymbolAddress((void**)&v,   g_v);
    cudaGetSymbolAddress((void**)&ctx, g_ctx);
    cudaGetSymbolAddress((void**)&x1,  g_x1);
    cudaGetSymbolAddress((void**)&fb,  g_fb);
    cudaGetSymbolAddress((void**)&hh,  g_hh);  cudaGetSymbolAddress((void**)&hl,  g_hl);
    cudaGetSymbolAddress((void**)&h2h, g_h2h); cudaGetSymbolAddress((void**)&h2l, g_h2l);
    cudaGetSymbolAddress((void**)&cxh, g_cxh); cudaGetSymbolAddress((void**)&cxl, g_cxl);
    cudaGetSymbolAddress((void**)&fah, g_fah); cudaGetSymbolAddress((void**)&fal, g_fal);
    cudaGetSymbolAddress((void**)&Wqh, g_Wqh); cudaGetSymbolAddress((void**)&Wql, g_Wql);
    cudaGetSymbolAddress((void**)&Wkh, g_Wkh); cudaGetSymbolAddress((void**)&Wkl, g_Wkl);
    cudaGetSymbolAddress((void**)&Wvh, g_Wvh); cudaGetSymbolAddress((void**)&Wvl, g_Wvl);
    cudaGetSymbolAddress((void**)&Woh, g_Woh); cudaGetSymbolAddress((void**)&Wol, g_Wol);
    cudaGetSymbolAddress((void**)&W1h, g_W1h); cudaGetSymbolAddress((void**)&W1l, g_W1l);
    cudaGetSymbolAddress((void**)&W2h, g_W2h); cudaGetSymbolAddress((void**)&W2l, g_W2l);
    cudaGetSymbolAddress((void**)&W3h, g_W3h); cudaGetSymbolAddress((void**)&W3l, g_W3l);

    cudaFuncSetAttribute(attn_kernel,
                         cudaFuncAttributeMaxDynamicSharedMemorySize, ATT_SMEM);

    dim3 tb(32, 8);
    // Weight prep: transpose + bf16 hi/lo split
    transpose_split_kernel<<<dim3(32, 32), tb>>>(Wq, Wqh, Wql, 1024, 1024, 1024, 1024);
    transpose_split_kernel<<<dim3(32, 32), tb>>>(Wk, Wkh, Wkl, 1024, 1024, 1024, 1024);
    transpose_split_kernel<<<dim3(32, 32), tb>>>(Wv, Wvh, Wvl, 1024, 1024, 1024, 1024);
    transpose_split_kernel<<<dim3(32, 32), tb>>>(Wo, Woh, Wol, 1024, 1024, 1024, 1024);
    transpose_split_kernel<<<dim3(32, 88), tb>>>(W1, W1h, W1l, 1024, DFFn, 1024, DFFp);
    transpose_split_kernel<<<dim3(32, 88), tb>>>(W2, W2h, W2l, 1024, DFFn, 1024, DFFp);
    transpose_split_kernel<<<dim3(86, 32), tb>>>(W3, W3h, W3l, DFFn, 1024, KFp, 1024);

    dim3 g8(8, 32), g22(22, 32);

    // h = rmsnorm(x, g1) -> bf16 hi/lo
    rmsnorm_split_kernel<<<Mn, 256>>>(x, g1, hh, hl);
    // QKV projections (HMMA)
    mma_gemm<0><<<g8, 256>>>(hh, hl, Wqh, Wql, nullptr, q, nullptr, nullptr,
                             1024, 1024, 1024, 1024, 1024);
    mma_gemm<0><<<g8, 256>>>(hh, hl, Wkh, Wkl, nullptr, k, nullptr, nullptr,
                             1024, 1024, 1024, 1024, 1024);
    mma_gemm<0><<<g8, 256>>>(hh, hl, Wvh, Wvl, nullptr, v, nullptr, nullptr,
                             1024, 1024, 1024, 1024, 1024);
    // causal attention
    attn_kernel<<<dim3(Tn / 64, Bn * Hn), 256, ATT_SMEM>>>(q, k, v, ctx);
    // split ctx for Wo GEMM
    split_kernel<<<Mn * Dn / 1024, 256>>>(ctx, cxh, cxl, Mn * Dn / 4);
    // x1 = x + ctx @ Wo
    mma_gemm<1><<<g8, 256>>>(cxh, cxl, Woh, Wol, x, x1, nullptr, nullptr,
                             1024, 1024, 1024, 1024, 1024);
    // h2 = rmsnorm(x1, g2) -> bf16 hi/lo
    rmsnorm_split_kernel<<<Mn, 256>>>(x1, g2, h2h, h2l);
    // fb = h2 @ W2 (fp32 out)
    mma_gemm<0><<<g22, 256>>>(h2h, h2l, W2h, W2l, nullptr, fb, nullptr, nullptr,
                              1024, DFFn, DFFn, DFFn, DFFn);
    // fa = split( silu(h2 @ W1) * fb )  (bf16 hi/lo, K-padded to 2752)
    mma_gemm<2><<<g22, 256>>>(h2h, h2l, W1h, W1l, fb, nullptr, fah, fal,
                              1024, KFp, DFFn, DFFn, KFp);
    // out = x1 + fa @ W3
    mma_gemm<1><<<g8, 256>>>(fah, fal, W3h, W3l, x1, out, nullptr, nullptr,
                             KFp, 1024, 1024, 1024, 1024);
}

// round 7
// speedup vs baseline: 2.9476x; 1.5400x over previous
#include <cuda_runtime.h>
#include <cuda_bf16.h>
#include <math.h>
#include <stdint.h>

// Problem constants
#define Bn   2
#define Tn   2048
#define Dn   1024
#define Hn   16
#define DHn  64
#define DFFn 2730
#define Mn   (Bn*Tn)          // 4096 rows
#define EPSn 1e-5f
#define DFFp 2816             // padded logical cols for W1/W2
#define NQKV 3072             // packed QKV output width
#define N12  5632             // 2*DFFp interleaved W1/W2 width
#define KFp  2752             // padded K for fa / W3 (86*32)

typedef unsigned long long u64;

__device__ __forceinline__ uint32_t smem_u32(const void* p) {
    uint32_t a;
    asm("{ .reg .u64 t; cvta.to.shared.u64 t, %1; cvt.u32.u64 %0, t; }"
        : "=r"(a) : "l"(p));
    return a;
}
__device__ __forceinline__ uint32_t pack_bf2(__nv_bfloat16 a, __nv_bfloat16 b) {
    return ((uint32_t)__bfloat16_as_ushort(b) << 16) | __bfloat16_as_ushort(a);
}
__device__ __forceinline__ void cp16(uint32_t d, const void* s) {
    asm volatile("cp.async.cg.shared.global [%0], [%1], 16;"
                 :: "r"(d), "l"(s) : "memory");
}
__device__ __forceinline__ void hmma(float* c, const uint32_t* a, const uint32_t* b) {
    asm volatile(
        "mma.sync.aligned.m16n8k16.row.col.f32.bf16.bf16.f32 "
        "{%0,%1,%2,%3}, {%4,%5,%6,%7}, {%8,%9}, {%0,%1,%2,%3};"
        : "+f"(c[0]), "+f"(c[1]), "+f"(c[2]), "+f"(c[3])
        : "r"(a[0]), "r"(a[1]), "r"(a[2]), "r"(a[3]), "r"(b[0]), "r"(b[1]));
}
__device__ __forceinline__ void ldsm_x4(uint32_t* r, uint32_t addr) {
    asm volatile("ldmatrix.sync.aligned.m8n8.x4.shared.b16 {%0,%1,%2,%3}, [%4];"
                 : "=r"(r[0]), "=r"(r[1]), "=r"(r[2]), "=r"(r[3]) : "r"(addr));
}
__device__ __forceinline__ void ldsm_x4t(uint32_t* r, uint32_t addr) {
    asm volatile("ldmatrix.sync.aligned.m8n8.x4.trans.shared.b16 {%0,%1,%2,%3}, [%4];"
                 : "=r"(r[0]), "=r"(r[1]), "=r"(r[2]), "=r"(r[3]) : "r"(addr));
}

// ---------------------------------------------------------------------------
// Scratch (device globals)
// ---------------------------------------------------------------------------
__device__ float g_x1 [Mn*Dn];

__device__ __nv_bfloat16 g_hh [Mn*Dn], g_hl [Mn*Dn];
__device__ __nv_bfloat16 g_h2h[Mn*Dn], g_h2l[Mn*Dn];
__device__ __nv_bfloat16 g_qkvh[(size_t)Mn*NQKV], g_qkvl[(size_t)Mn*NQKV];
__device__ __nv_bfloat16 g_cxh[Mn*Dn], g_cxl[Mn*Dn];
__device__ __nv_bfloat16 g_fah[(size_t)Mn*KFp], g_fal[(size_t)Mn*KFp];
__device__ __nv_bfloat16 g_Wqkvh[(size_t)NQKV*Dn], g_Wqkvl[(size_t)NQKV*Dn];
__device__ __nv_bfloat16 g_Woh[Dn*Dn],  g_Wol[Dn*Dn];
__device__ __nv_bfloat16 g_W12h[(size_t)N12*Dn], g_W12l[(size_t)N12*Dn];
__device__ __nv_bfloat16 g_W3h[(size_t)Dn*KFp],  g_W3l[(size_t)Dn*KFp];

// ---------------------------------------------------------------------------
// RMSNorm with bf16 hi/lo split output
// ---------------------------------------------------------------------------
__global__ void rmsnorm_split_kernel(const float* __restrict__ x,
                                     const float* __restrict__ g,
                                     __nv_bfloat16* __restrict__ oh,
                                     __nv_bfloat16* __restrict__ ol) {
    const int row = blockIdx.x;
    const int t   = threadIdx.x;
    const float4* xr = (const float4*)(x + (size_t)row * Dn);
    float4 xv = xr[t];
    float ss = xv.x*xv.x + xv.y*xv.y + xv.z*xv.z + xv.w*xv.w;
    #pragma unroll
    for (int o = 16; o > 0; o >>= 1) ss += __shfl_xor_sync(0xffffffffu, ss, o);
    __shared__ float red[8];
    if ((t & 31) == 0) red[t >> 5] = ss;
    __syncthreads();
    float tot = red[0]+red[1]+red[2]+red[3]+red[4]+red[5]+red[6]+red[7];
    float rs = rsqrtf(tot * (1.0f / Dn) + EPSn);
    float4 gv = ((const float4*)g)[t];
    float o0 = gv.x*xv.x*rs, o1 = gv.y*xv.y*rs, o2 = gv.z*xv.z*rs, o3 = gv.w*xv.w*rs;
    __nv_bfloat16 h0 = __float2bfloat16(o0), h1 = __float2bfloat16(o1);
    __nv_bfloat16 h2 = __float2bfloat16(o2), h3 = __float2bfloat16(o3);
    __nv_bfloat16 l0 = __float2bfloat16(o0 - __bfloat162float(h0));
    __nv_bfloat16 l1 = __float2bfloat16(o1 - __bfloat162float(h1));
    __nv_bfloat16 l2 = __float2bfloat16(o2 - __bfloat162float(h2));
    __nv_bfloat16 l3 = __float2bfloat16(o3 - __bfloat162float(h3));
    uint2 uh = make_uint2(pack_bf2(h0,h1), pack_bf2(h2,h3));
    uint2 ul = make_uint2(pack_bf2(l0,l1), pack_bf2(l2,l3));
    *(uint2*)&oh[(size_t)row*Dn + t*4] = uh;
    *(uint2*)&ol[(size_t)row*Dn + t*4] = ul;
}

// ---------------------------------------------------------------------------
// Weight transpose + split: W[K,N] fp32 -> T_hi/lo at row n*rowMul+rowOff, [*, Kp]
// ---------------------------------------------------------------------------
__global__ void transpose_split_kernel(const float* __restrict__ W,
                                       __nv_bfloat16* __restrict__ Th,
                                       __nv_bfloat16* __restrict__ Tl,
                                       int K, int N, int Kp, int Np,
                                       int rowMul, int rowOff) {
    __shared__ float tile[32][33];
    int kb = blockIdx.x * 32, nb = blockIdx.y * 32;
    int tx = threadIdx.x, ty = threadIdx.y;   // 32 x 8
    #pragma unroll
    for (int i = 0; i < 32; i += 8) {
        int k = kb + ty + i, n = nb + tx;
        tile[ty + i][tx] = (k < K && n < N) ? W[(size_t)k * N + n] : 0.0f;
    }
    __syncthreads();
    #pragma unroll
    for (int i = 0; i < 32; i += 8) {
        int n = nb + ty + i, k = kb + tx;
        if (n < Np && k < Kp) {
            float v = tile[tx][ty + i];
            __nv_bfloat16 h = __float2bfloat16(v);
            size_t r = (size_t)n * rowMul + rowOff;
            Th[r * Kp + k] = h;
            Tl[r * Kp + k] = __float2bfloat16(v - __bfloat162float(h));
        }
    }
}

// ---------------------------------------------------------------------------
// HMMA split-bf16 GEMM: D[M,N] = (Ah+Al)[M,K] @ (Bh+Bl)^T, Bt = [N,K] bf16.
// MODE 1: Out = D + Res (fp32)
// MODE 3: Oh/Ol = split(D * (col<aux ? 0.125 : 1))           (QKV)
// MODE 4: interleaved swiglu: pairs (W1,W2); logical col=col/2; guard lc<aux;
//         Oh/Ol = split(silu(v0)*v1) at [row*outStride + lc]  (scalar bf16)
// ---------------------------------------------------------------------------
#define ROWB 80

template<int MODE>
__global__ void __launch_bounds__(256, 2)
mma_gemm(const __nv_bfloat16* __restrict__ Ah, const __nv_bfloat16* __restrict__ Al,
         const __nv_bfloat16* __restrict__ Bh, const __nv_bfloat16* __restrict__ Bl,
         const float* __restrict__ Res, float* __restrict__ Out,
         __nv_bfloat16* __restrict__ Oh, __nv_bfloat16* __restrict__ Ol,
         int K, int Nout, int aux, int resStride, int outStride) {
    __shared__ __align__(16) char Asm[2][128 * ROWB];
    __shared__ __align__(16) char Bsm[2][128 * ROWB];

    const int tid  = threadIdx.x;
    const int wid  = tid >> 5, lane = tid & 31;
    const int wM = (wid >> 2) * 64, wN = (wid & 3) * 32;
    const int rowBase = blockIdx.y * 128;
    const int colBase = blockIdx.x * 128;

    float acc[4][4][4];
    #pragma unroll
    for (int mi = 0; mi < 4; ++mi)
        #pragma unroll
        for (int ni = 0; ni < 4; ++ni)
            #pragma unroll
            for (int e = 0; e < 4; ++e) acc[mi][ni][e] = 0.0f;

    const int cpp = K >> 5;
    const int nch = 3 * cpp;

    auto issue = [&](int c) {
        const int pass = c / cpp;
        const int k0 = (c - pass * cpp) << 5;
        const __nv_bfloat16* As = (pass == 2) ? Al : Ah;
        const __nv_bfloat16* Bs = (pass == 1) ? Bl : Bh;
        char* ab = Asm[c & 1];
        char* bb = Bsm[c & 1];
        #pragma unroll
        for (int l = 0; l < 2; ++l) {
            int idx = tid + (l << 8);
            int row = idx >> 2, ch = idx & 3;
            uint32_t so = (uint32_t)(row * ROWB + ch * 16);
            cp16(smem_u32(ab + so), As + (size_t)(rowBase + row) * K + k0 + ch * 8);
            cp16(smem_u32(bb + so), Bs + (size_t)(colBase + row) * K + k0 + ch * 8);
        }
        asm volatile("cp.async.commit_group;" ::: "memory");
    };

    issue(0);
    for (int c = 0; c < nch; ++c) {
        if (c + 1 < nch) {
            issue(c + 1);
            asm volatile("cp.async.wait_group 1;" ::: "memory");
        } else {
            asm volatile("cp.async.wait_group 0;" ::: "memory");
        }
        __syncthreads();

        const char* ab = Asm[c & 1];
        const char* bb = Bsm[c & 1];
        #pragma unroll
        for (int ks = 0; ks < 2; ++ks) {
            uint32_t a[4][4], b[4][2];
            #pragma unroll
            for (int mi = 0; mi < 4; ++mi) {
                uint32_t ad = smem_u32(ab + (wM + mi * 16 + (lane & 15)) * ROWB
                                          + ks * 32 + ((lane >> 4) & 1) * 16);
                ldsm_x4(a[mi], ad);
            }
            #pragma unroll
            for (int ni = 0; ni < 4; ++ni) {
                uint32_t bd = smem_u32(bb + (wN + ni * 8 + (lane & 7)) * ROWB
                                          + ks * 32 + ((lane >> 3) & 1) * 16);
                asm volatile("ldmatrix.sync.aligned.m8n8.x2.shared.b16 {%0,%1}, [%2];"
                             : "=r"(b[ni][0]), "=r"(b[ni][1]) : "r"(bd));
            }
            #pragma unroll
            for (int mi = 0; mi < 4; ++mi)
                #pragma unroll
                for (int ni = 0; ni < 4; ++ni)
                    hmma(acc[mi][ni], a[mi], b[ni]);
        }
        __syncthreads();
    }

    #pragma unroll
    for (int mi = 0; mi < 4; ++mi) {
        #pragma unroll
        for (int ni = 0; ni < 4; ++ni) {
            int col = colBase + wN + ni * 8 + (lane & 3) * 2;
            if (col >= Nout) continue;
            int r0 = rowBase + wM + mi * 16 + (lane >> 2);
            #pragma unroll
            for (int half = 0; half < 2; ++half) {
                int row = r0 + half * 8;
                float v0 = acc[mi][ni][half * 2];
                float v1 = acc[mi][ni][half * 2 + 1];
                if (MODE == 1) {
                    float2 r = *(const float2*)&Res[(size_t)row * resStride + col];
                    v0 += r.x; v1 += r.y;
                    *(float2*)&Out[(size_t)row * outStride + col] = make_float2(v0, v1);
                } else if (MODE == 3) {
                    float sc = (col < aux) ? 0.125f : 1.0f;
                    v0 *= sc; v1 *= sc;
                    __nv_bfloat16 h0 = __float2bfloat16(v0), h1 = __float2bfloat16(v1);
                    __nv_bfloat16 l0 = __float2bfloat16(v0 - __bfloat162float(h0));
                    __nv_bfloat16 l1 = __float2bfloat16(v1 - __bfloat162float(h1));
                    *(uint32_t*)&Oh[(size_t)row * outStride + col] = pack_bf2(h0, h1);
                    *(uint32_t*)&Ol[(size_t)row * outStride + col] = pack_bf2(l0, l1);
                } else if (MODE == 4) {
                    int lc = col >> 1;
                    if (lc < aux) {
                        float u = v0 / (1.0f + __expf(-v0)) * v1;
                        __nv_bfloat16 h = __float2bfloat16(u);
                        __nv_bfloat16 l = __float2bfloat16(u - __bfloat162float(h));
                        Oh[(size_t)row * outStride + lc] = h;
                        Ol[(size_t)row * outStride + lc] = l;
                    }
                }
            }
        }
    }
}

// ---------------------------------------------------------------------------
// HMMA flash attention: causal, Q pre-scaled by 0.125 in QKV epilogue.
// ALiBi bias is identically zero on the causal region.
// BQ=128, BK=64, 8 warps (16 q-rows each). Split-bf16 on both GEMMs:
//   S = QhKh + QlKh + QhKl ;  O += PhVh + PlVh + PhVl
// ---------------------------------------------------------------------------
#define AQS 72                                  // smem row stride (bf16 elems)
#define ATT_SMEM ((2*128 + 8*64) * AQS * 2)     // 110,592 bytes

__global__ void __launch_bounds__(256, 1)
attn_hmma(const __nv_bfloat16* __restrict__ qkvh,
          const __nv_bfloat16* __restrict__ qkvl,
          __nv_bfloat16* __restrict__ cxh,
          __nv_bfloat16* __restrict__ cxl) {
    extern __shared__ __align__(16) char smb[];
    __nv_bfloat16* Qh = (__nv_bfloat16*)smb;
    __nv_bfloat16* Ql = Qh + 128 * AQS;
    __nv_bfloat16* KV = Ql + 128 * AQS;     // [buf(2)][arr(4)][64][AQS]

    const int qt = 15 - blockIdx.x;
    const int bh = blockIdx.y, b = bh >> 4, h = bh & 15;
    const int tid = threadIdx.x, wid = tid >> 5, lane = tid & 31;
    const int wrow = wid * 16;
    const size_t base = (size_t)b * 2048 * NQKV + h * 64;
    const __nv_bfloat16* srcs[6] = {
        qkvh + base,        qkvl + base,           // Qh, Ql
        qkvh + base + 1024, qkvl + base + 1024,    // Kh, Kl
        qkvh + base + 2048, qkvl + base + 2048 };  // Vh, Vl

    // Q load (both bufs) — group 0 together with kv tile 0
    #pragma unroll
    for (int l = 0; l < 8; ++l) {
        int flat = tid + (l << 8);
        int bq = flat >> 10, rem = flat & 1023;
        int row = rem >> 3, ch = rem & 7;
        const __nv_bfloat16* src = srcs[bq] + (size_t)(qt * 128 + row) * NQKV + ch * 8;
        __nv_bfloat16* dst = (bq ? Ql : Qh) + row * AQS + ch * 8;
        cp16(smem_u32(dst), src);
    }
    auto issueKV = [&](int kt) {
        int buf = kt & 1;
        #pragma unroll
        for (int l = 0; l < 8; ++l) {
            int flat = tid + (l << 8);
            int arr = flat >> 9, rem = flat & 511;
            int row = rem >> 3, ch = rem & 7;
            const __nv_bfloat16* src = srcs[2 + arr]
                                     + (size_t)(kt * 64 + row) * NQKV + ch * 8;
            __nv_bfloat16* dst = KV + ((buf * 4 + arr) * 64 + row) * AQS + ch * 8;
            cp16(smem_u32(dst), src);
        }
        asm volatile("cp.async.commit_group;" ::: "memory");
    };

    const int nk = 2 * (qt + 1);
    issueKV(0);                       // group 0 (with Q)
    issueKV(1);                       // group 1 (nk >= 2 always)

    float o[8][4];
    #pragma unroll
    for (int j = 0; j < 8; ++j)
        #pragma unroll
        for (int e = 0; e < 4; ++e) o[j][e] = 0.0f;
    float m0 = -1e30f, m1 = -1e30f, l0 = 0.0f, l1 = 0.0f;

    for (int kt = 0; kt < nk; ++kt) {
        if (kt + 1 < nk)
            asm volatile("cp.async.wait_group 1;" ::: "memory");
        else
            asm volatile("cp.async.wait_group 0;" ::: "memory");
        __syncthreads();

        const int buf = kt & 1;
        const __nv_bfloat16* KhT = KV + (buf * 4 + 0) * 64 * AQS;
        const __nv_bfloat16* KlT = KV + (buf * 4 + 1) * 64 * AQS;
        const __nv_bfloat16* VhT = KV + (buf * 4 + 2) * 64 * AQS;
        const __nv_bfloat16* VlT = KV + (buf * 4 + 3) * 64 * AQS;

        // ---- S = Q K^T (3 split passes), fp32 frags
        float s[8][4];
        #pragma unroll
        for (int j = 0; j < 8; ++j)
            #pragma unroll
            for (int e = 0; e < 4; ++e) s[j][e] = 0.0f;

        #pragma unroll
        for (int t = 0; t < 4; ++t) {
            uint32_t aqh[4], aql[4], kb[8][2];
            uint32_t qoff = (uint32_t)((wrow + (lane & 15)) * AQS * 2
                                       + t * 32 + ((lane >> 4) & 1) * 16);
            ldsm_x4(aqh, smem_u32((const char*)Qh + qoff));
            ldsm_x4(aql, smem_u32((const char*)Ql + qoff));
            #pragma unroll
            for (int jj = 0; jj < 4; ++jj) {      // Kh b-frags (2 nfrags per x4)
                uint32_t tmp[4];
                uint32_t koff = (uint32_t)((jj * 16 + (lane & 15)) * AQS * 2
                                           + t * 32 + ((lane >> 4) & 1) * 16);
                ldsm_x4(tmp, smem_u32((const char*)KhT + koff));
                kb[2*jj][0] = tmp[0]; kb[2*jj][1] = tmp[2];
                kb[2*jj+1][0] = tmp[1]; kb[2*jj+1][1] = tmp[3];
            }
            #pragma unroll
            for (int j = 0; j < 8; ++j) hmma(s[j], aqh, kb[j]);
            #pragma unroll
            for (int j = 0; j < 8; ++j) hmma(s[j], aql, kb[j]);
            #pragma unroll
            for (int jj = 0; jj < 4; ++jj) {      // Kl b-frags
                uint32_t tmp[4];
                uint32_t koff = (uint32_t)((jj * 16 + (lane & 15)) * AQS * 2
                                           + t * 32 + ((lane >> 4) & 1) * 16);
                ldsm_x4(tmp, smem_u32((const char*)KlT + koff));
                kb[2*jj][0] = tmp[0]; kb[2*jj][1] = tmp[2];
                kb[2*jj+1][0] = tmp[1]; kb[2*jj+1][1] = tmp[3];
            }
            #pragma unroll
            for (int j = 0; j < 8; ++j) hmma(s[j], aqh, kb[j]);
        }

        // ---- causal mask (only last two tiles can overlap diagonal)
        if (kt >= 2 * qt) {
            int row0 = qt * 128 + wrow + (lane >> 2);
            #pragma unroll
            for (int j = 0; j < 8; ++j) {
                int c = kt * 64 + 8 * j + 2 * (lane & 3);
                if (c     > row0)     s[j][0] = -1e30f;
                if (c + 1 > row0)     s[j][1] = -1e30f;
                if (c     > row0 + 8) s[j][2] = -1e30f;
                if (c + 1 > row0 + 8) s[j][3] = -1e30f;
            }
        }

        // ---- online softmax (2 rows per thread; 4-lane groups share rows)
        float rm0 = -1e30f, rm1 = -1e30f;
        #pragma unroll
        for (int j = 0; j < 8; ++j) {
            rm0 = fmaxf(rm0, fmaxf(s[j][0], s[j][1]));
            rm1 = fmaxf(rm1, fmaxf(s[j][2], s[j][3]));
        }
        rm0 = fmaxf(rm0, __shfl_xor_sync(0xffffffffu, rm0, 1));
        rm0 = fmaxf(rm0, __shfl_xor_sync(0xffffffffu, rm0, 2));
        rm1 = fmaxf(rm1, __shfl_xor_sync(0xffffffffu, rm1, 1));
        rm1 = fmaxf(rm1, __shfl_xor_sync(0xffffffffu, rm1, 2));
        float mn0 = fmaxf(m0, rm0), mn1 = fmaxf(m1, rm1);
        float sc0 = __expf(m0 - mn0), sc1 = __expf(m1 - mn1);
        m0 = mn0; m1 = mn1;

        float sum0 = 0.0f, sum1 = 0.0f;
        uint32_t pha[8], phb[8], pla[8], plb[8];
        #pragma unroll
        for (int j = 0; j < 8; ++j) {
            float p0 = __expf(s[j][0] - mn0), p1 = __expf(s[j][1] - mn0);
            float p2 = __expf(s[j][2] - mn1), p3 = __expf(s[j][3] - mn1);
            sum0 += p0 + p1; sum1 += p2 + p3;
            __nv_bfloat16 h0 = __float2bfloat16(p0), h1 = __float2bfloat16(p1);
            __nv_bfloat16 h2 = __float2bfloat16(p2), h3 = __float2bfloat16(p3);
            pha[j] = pack_bf2(h0, h1); phb[j] = pack_bf2(h2, h3);
            pla[j] = pack_bf2(__float2bfloat16(p0 - __bfloat162float(h0)),
                              __float2bfloat16(p1 - __bfloat162float(h1)));
            plb[j] = pack_bf2(__float2bfloat16(p2 - __bfloat162float(h2)),
                              __float2bfloat16(p3 - __bfloat162float(h3)));
        }
        sum0 += __shfl_xor_sync(0xffffffffu, sum0, 1);
        sum0 += __shfl_xor_sync(0xffffffffu, sum0, 2);
        sum1 += __shfl_xor_sync(0xffffffffu, sum1, 1);
        sum1 += __shfl_xor_sync(0xffffffffu, sum1, 2);
        l0 = l0 * sc0 + sum0;
        l1 = l1 * sc1 + sum1;
        #pragma unroll
        for (int j = 0; j < 8; ++j) {
            o[j][0] *= sc0; o[j][1] *= sc0; o[j][2] *= sc1; o[j][3] *= sc1;
        }

        // ---- O += P V (3 split passes)
        #pragma unroll
        for (int t = 0; t < 4; ++t) {
            uint32_t ah[4] = {pha[2*t], phb[2*t], pha[2*t+1], phb[2*t+1]};
            uint32_t al[4] = {pla[2*t], plb[2*t], pla[2*t+1], plb[2*t+1]};
            #pragma unroll
            for (int jd = 0; jd < 4; ++jd) {     // nfrag pairs: dh cols 16jd
                uint32_t vb[4];
                uint32_t voff = (uint32_t)((t * 16 + (lane & 15)) * AQS * 2
                                           + jd * 32 + ((lane >> 4) & 1) * 16);
                ldsm_x4t(vb, smem_u32((const char*)VhT + voff));
                uint32_t b0[2] = {vb[0], vb[1]}, b1[2] = {vb[2], vb[3]};
                hmma(o[2*jd],   ah, b0); hmma(o[2*jd+1], ah, b1);
                hmma(o[2*jd],   al, b0); hmma(o[2*jd+1], al, b1);
                ldsm_x4t(vb, smem_u32((const char*)VlT + voff));
                uint32_t c0[2] = {vb[0], vb[1]}, c1[2] = {vb[2], vb[3]};
                hmma(o[2*jd],   ah, c0); hmma(o[2*jd+1], ah, c1);
            }
        }
        __syncthreads();
        if (kt + 2 < nk) issueKV(kt + 2);
    }

    // ---- write O as bf16 hi/lo
    float inv0 = 1.0f / l0, inv1 = 1.0f / l1;
    int row0 = b * 2048 + qt * 128 + wrow + (lane >> 2);
    #pragma unroll
    for (int j = 0; j < 8; ++j) {
        int col = h * 64 + 8 * j + 2 * (lane & 3);
        float v0 = o[j][0] * inv0, v1 = o[j][1] * inv0;
        float v2 = o[j][2] * inv1, v3 = o[j][3] * inv1;
        __nv_bfloat16 h0 = __float2bfloat16(v0), h1 = __float2bfloat16(v1);
        __nv_bfloat16 h2 = __float2bfloat16(v2), h3 = __float2bfloat16(v3);
        *(uint32_t*)&cxh[(size_t)row0 * Dn + col] = pack_bf2(h0, h1);
        *(uint32_t*)&cxl[(size_t)row0 * Dn + col] =
            pack_bf2(__float2bfloat16(v0 - __bfloat162float(h0)),
                     __float2bfloat16(v1 - __bfloat162float(h1)));
        *(uint32_t*)&cxh[(size_t)(row0 + 8) * Dn + col] = pack_bf2(h2, h3);
        *(uint32_t*)&cxl[(size_t)(row0 + 8) * Dn + col] =
            pack_bf2(__float2bfloat16(v2 - __bfloat162float(h2)),
                     __float2bfloat16(v3 - __bfloat162float(h3)));
    }
}

// ---------------------------------------------------------------------------
// Launch
// ---------------------------------------------------------------------------
extern "C" void kernel_launch(void* const* d_in, const int* in_sizes, int n_in,
                              void* d_out, int out_size) {
    const float* x  = (const float*)d_in[0];
    const float* g1 = (const float*)d_in[1];
    const float* Wq = (const float*)d_in[2];
    const float* Wk = (const float*)d_in[3];
    const float* Wv = (const float*)d_in[4];
    const float* Wo = (const float*)d_in[5];
    const float* g2 = (const float*)d_in[6];
    const float* W1 = (const float*)d_in[7];
    const float* W2 = (const float*)d_in[8];
    const float* W3 = (const float*)d_in[9];
    float* out = (float*)d_out;

    float *x1;
    __nv_bfloat16 *hh,*hl,*h2h,*h2l,*qkvh,*qkvl,*cxh,*cxl,*fah,*fal;
    __nv_bfloat16 *Wqkvh,*Wqkvl,*Woh,*Wol,*W12h,*W12l,*W3h,*W3l;
    cudaGetSymbolAddress((void**)&x1,  g_x1);
    cudaGetSymbolAddress((void**)&hh,  g_hh);   cudaGetSymbolAddress((void**)&hl,  g_hl);
    cudaGetSymbolAddress((void**)&h2h, g_h2h);  cudaGetSymbolAddress((void**)&h2l, g_h2l);
    cudaGetSymbolAddress((void**)&qkvh,g_qkvh); cudaGetSymbolAddress((void**)&qkvl,g_qkvl);
    cudaGetSymbolAddress((void**)&cxh, g_cxh);  cudaGetSymbolAddress((void**)&cxl, g_cxl);
    cudaGetSymbolAddress((void**)&fah, g_fah);  cudaGetSymbolAddress((void**)&fal, g_fal);
    cudaGetSymbolAddress((void**)&Wqkvh,g_Wqkvh);cudaGetSymbolAddress((void**)&Wqkvl,g_Wqkvl);
    cudaGetSymbolAddress((void**)&Woh, g_Woh);  cudaGetSymbolAddress((void**)&Wol, g_Wol);
    cudaGetSymbolAddress((void**)&W12h,g_W12h); cudaGetSymbolAddress((void**)&W12l,g_W12l);
    cudaGetSymbolAddress((void**)&W3h, g_W3h);  cudaGetSymbolAddress((void**)&W3l, g_W3l);

    cudaFuncSetAttribute(attn_hmma,
                         cudaFuncAttributeMaxDynamicSharedMemorySize, ATT_SMEM);

    dim3 tb(32, 8);
    // QKV packed [3072][1024]
    transpose_split_kernel<<<dim3(32,32), tb>>>(Wq, Wqkvh, Wqkvl,
                                                1024,1024,1024,1024, 1, 0);
    transpose_split_kernel<<<dim3(32,32), tb>>>(Wk, Wqkvh + 1024*1024,
                                                Wqkvl + 1024*1024,
                                                1024,1024,1024,1024, 1, 0);
    transpose_split_kernel<<<dim3(32,32), tb>>>(Wv, Wqkvh + 2048*1024,
                                                Wqkvl + 2048*1024,
                                                1024,1024,1024,1024, 1, 0);
    transpose_split_kernel<<<dim3(32,32), tb>>>(Wo, Woh, Wol,
                                                1024,1024,1024,1024, 1, 0);
    // W1/W2 column-interleaved packed [5632][1024]
    transpose_split_kernel<<<dim3(32,88), tb>>>(W1, W12h, W12l,
                                                1024,DFFn,1024,DFFp, 2, 0);
    transpose_split_kernel<<<dim3(32,88), tb>>>(W2, W12h, W12l,
                                                1024,DFFn,1024,DFFp, 2, 1);
    // W3 [1024][2752]
    transpose_split_kernel<<<dim3(86,32), tb>>>(W3, W3h, W3l,
                                                DFFn,1024,KFp,1024, 1, 0);

    // h = rmsnorm(x, g1) -> bf16 hi/lo
    rmsnorm_split_kernel<<<Mn, 256>>>(x, g1, hh, hl);
    // QKV = h @ Wqkv, split-bf16 out, Q scaled by 0.125
    mma_gemm<3><<<dim3(24,32), 256>>>(hh, hl, Wqkvh, Wqkvl, nullptr, nullptr,
                                      qkvh, qkvl, 1024, NQKV, 1024, 0, NQKV);
    // causal attention -> ctx bf16 hi/lo
    attn_hmma<<<dim3(16, Bn*Hn), 256, ATT_SMEM>>>(qkvh, qkvl, cxh, cxl);
    // x1 = x + ctx @ Wo
    mma_gemm<1><<<dim3(8,32), 256>>>(cxh, cxl, Woh, Wol, x, x1, nullptr, nullptr,
                                     1024, 1024, 0, 1024, 1024);
    // h2 = rmsnorm(x1, g2)
    rmsnorm_split_kernel<<<Mn, 256>>>(x1, g2, h2h, h2l);
    // fused SwiGLU: fa = split( silu(h2@W1) * (h2@W2) )  (interleaved N)
    mma_gemm<4><<<dim3(44,32), 256>>>(h2h, h2l, W12h, W12l, nullptr, nullptr,
                                      fah, fal, 1024, N12, KFp, 0, KFp);
    // out = x1 + fa @ W3
    mma_gemm<1><<<dim3(8,32), 256>>>(fah, fal, W3h, W3l, x1, out, nullptr, nullptr,
                                     KFp, 1024, 0, 1024, 1024);
}